// round 10
// baseline (speedup 1.0000x reference)
#include <cuda_runtime.h>
#include <cuda_fp16.h>
#include <cstdint>

#define TOK 16384
#define TPAD 16640
#define DD 2048
#define FF 5632
#define STAGE 49152

// ---------------- device scratch ----------------
__device__ int g_meta[8];          // 0 cnt0, 1 cnt1, 2 pos0, 3 pos1, 4 M0pad, 5 Mtot
__device__ int g_rows[TPAD];
__device__ __align__(128) __half g_Xh[(size_t)TPAD * DD];
__device__ __align__(128) __half g_Wg[(size_t)2 * FF * DD];   // [e][FF][D] K-major
__device__ __align__(128) __half g_Wu[(size_t)2 * FF * DD];
__device__ __align__(128) __half g_Wd[(size_t)2 * DD * FF];   // [e][D][FF] K-major
__device__ __align__(128) __half g_Hh[(size_t)TPAD * FF];

// ---------------- helpers ----------------
__device__ __forceinline__ uint32_t sptr(const void* p) {
    uint32_t a;
    asm("{.reg .u64 t; cvta.to.shared.u64 t,%1; cvt.u32.u64 %0,t;}" : "=r"(a) : "l"(p));
    return a;
}
__device__ __forceinline__ void cpa(uint32_t d, const void* s) {
    asm volatile("cp.async.cg.shared.global [%0],[%1],16;" :: "r"(d), "l"(s));
}
__device__ __forceinline__ void cpcommit() { asm volatile("cp.async.commit_group;"); }
template <int N> __device__ __forceinline__ void cpwait() {
    asm volatile("cp.async.wait_group %0;" :: "n"(N));
}
__device__ __forceinline__ uint32_t sw(uint32_t o) { return o ^ ((o >> 3) & 0x70); }
__device__ __forceinline__ void ldsm4(uint32_t* r, uint32_t a) {
    asm volatile("ldmatrix.sync.aligned.m8n8.x4.shared.b16 {%0,%1,%2,%3},[%4];"
                 : "=r"(r[0]), "=r"(r[1]), "=r"(r[2]), "=r"(r[3]) : "r"(a));
}
__device__ __forceinline__ void mma(float* c, const uint32_t* a, uint32_t b0, uint32_t b1) {
    asm volatile("mma.sync.aligned.m16n8k16.row.col.f32.f16.f16.f32 "
                 "{%0,%1,%2,%3},{%4,%5,%6,%7},{%8,%9},{%0,%1,%2,%3};"
                 : "+f"(c[0]), "+f"(c[1]), "+f"(c[2]), "+f"(c[3])
                 : "r"(a[0]), "r"(a[1]), "r"(a[2]), "r"(a[3]), "r"(b0), "r"(b1));
}

// ---------------- routing ----------------
__global__ void k_zero() { g_meta[0] = 0; g_meta[1] = 0; }
__global__ void k_count(const int* mask) {
    int t = blockIdx.x * 256 + threadIdx.x;
    if (t < TOK) atomicAdd(&g_meta[mask[t] != 0 ? 1 : 0], 1);
}
__global__ void k_metak() {
    int m0 = (g_meta[0] + 127) & ~127, m1 = (g_meta[1] + 127) & ~127;
    g_meta[4] = m0; g_meta[5] = m0 + m1; g_meta[2] = 0; g_meta[3] = m0;
}
__global__ void k_init() {
    int i = blockIdx.x * 256 + threadIdx.x;
    if (i < TPAD) g_rows[i] = -1;
}
__global__ void k_assign(const int* mask) {
    int t = blockIdx.x * 256 + threadIdx.x;
    if (t < TOK) {
        int e = mask[t] != 0;
        int r = atomicAdd(&g_meta[2 + e], 1);
        g_rows[r] = t;
    }
}
__global__ void k_xsplit(const float* X) {
    size_t i = (size_t)blockIdx.x * 256 + threadIdx.x;
    size_t row = i / (DD / 4);
    int c4 = (int)(i % (DD / 4));
    if (row >= (size_t)g_meta[5]) return;
    int t = g_rows[row];
    float4 v = t >= 0 ? ((const float4*)X)[(size_t)t * (DD / 4) + c4] : make_float4(0, 0, 0, 0);
    size_t o = row * DD + (size_t)c4 * 4;
    *(__half2*)(g_Xh + o) = __halves2half2(__float2half_rn(v.x), __float2half_rn(v.y));
    *(__half2*)(g_Xh + o + 2) = __halves2half2(__float2half_rn(v.z), __float2half_rn(v.w));
}
// transpose+convert: src fp32 [R,C] -> dst fp16 [C,R], per expert (z)
__global__ void k_tr(const float* src, __half* dst, int R, int C) {
    __shared__ float t[32][33];
    size_t eo = (size_t)blockIdx.z * R * C;
    src += eo; dst += eo;
    int c0 = blockIdx.x * 32, r0 = blockIdx.y * 32;
    int x = threadIdx.x, y = threadIdx.y;
    for (int i = y; i < 32; i += 8) t[i][x] = src[(size_t)(r0 + i) * C + c0 + x];
    __syncthreads();
    for (int i = y; i < 32; i += 8) dst[(size_t)(c0 + i) * R + r0 + x] = __float2half_rn(t[x][i]);
}

// ---------------- shared GEMM core ----------------
// 256 threads, 8 warps (2m x 4n), warptile 64x64. smem stage 48KB: A@0, B@16K.
// 3 stages, 1 barrier/chunk. B rows 0-127 from B0, 128-255 from B1.
__device__ __forceinline__ void gemm_main(
    const __half* A0, const __half* B0, const __half* B1,
    int lda, int ldb, int NK, uint32_t sb, int tid, const int* pb,
    float acc[4][8][4])
{
    int lane = tid & 31, wid = tid >> 5, mw = wid & 1;
    #pragma unroll
    for (int a = 0; a < 4; a++)
        #pragma unroll
        for (int j = 0; j < 8; j++)
            #pragma unroll
            for (int q = 0; q < 4; q++) acc[a][j][q] = 0.f;

    // hoisted per-thread load addressing (256 threads: A 4 ops, B 8 ops)
    const __half* srcA[4]; uint32_t dstA[4];
    #pragma unroll
    for (int j = 0; j < 4; j++) {
        int i = tid + j * 256, r = i >> 3, u = i & 7;
        srcA[j] = A0 + (size_t)r * lda + u * 8;
        dstA[j] = sw(r * 128 + u * 16);
    }
    const __half* srcB[8]; uint32_t dstB[8];
    #pragma unroll
    for (int j = 0; j < 8; j++) {
        int i = tid + j * 256, r = i >> 3, u = i & 7;
        srcB[j] = (r < 128 ? B0 + (size_t)r * ldb : B1 + (size_t)(r - 128) * ldb) + u * 8;
        dstB[j] = 16384 + sw(r * 128 + u * 16);
    }
    auto load = [&](int s3) {
        uint32_t st = sb + s3 * STAGE;
        #pragma unroll
        for (int j = 0; j < 4; j++) { cpa(st + dstA[j], srcA[j]); srcA[j] += 64; }
        #pragma unroll
        for (int j = 0; j < 8; j++) { cpa(st + dstB[j], srcB[j]); srcB[j] += 64; }
        cpcommit();
    };

    load(0); load(1);

    int ar = mw * 64 + (lane & 7) + ((lane >> 3) & 1) * 8;
    int akb = ((lane >> 4) & 1) * 16;
    int br = (lane & 7) + ((lane >> 4) & 1) * 8;
    int bkb = ((lane >> 3) & 1) * 16;

    int s = 0;
    for (int kc = 0; kc < NK; kc++) {
        if (kc + 1 < NK) cpwait<1>(); else cpwait<0>();
        __syncthreads();
        int sn = s + 2 >= 3 ? s - 1 : s + 2;
        if (kc + 2 < NK) load(sn);
        uint32_t st = sb + s * STAGE;
        #pragma unroll
        for (int ks = 0; ks < 4; ks++) {
            int kb = ks * 32;
            uint32_t a[4][4];
            #pragma unroll
            for (int mt = 0; mt < 4; mt++)
                ldsm4(a[mt], st + sw((ar + mt * 16) * 128 + kb + akb));
            #pragma unroll
            for (int p = 0; p < 4; p++) {
                uint32_t bb[4];
                ldsm4(bb, st + 16384 + sw((pb[p] + br) * 128 + kb + bkb));
                #pragma unroll
                for (int h = 0; h < 2; h++) {
                    int j = 2 * p + h;
                    #pragma unroll
                    for (int mt = 0; mt < 4; mt++)
                        mma(acc[mt][j], a[mt], bb[2 * h], bb[2 * h + 1]);
                }
            }
        }
        s = s + 1 >= 3 ? 0 : s + 1;
    }
}

// ---------------- GEMM1: X @ {Wg,Wu}^T -> SwiGLU -> H ----------------
__global__ void __launch_bounds__(256, 1) k_gemm1() {
    extern __shared__ __align__(1024) char smem[];
    int nt = blockIdx.x, mtb = blockIdx.y * 128;
    if (mtb >= g_meta[5]) return;
    int e = (mtb >= g_meta[4]) ? 1 : 0;
    int tid = threadIdx.x, lane = tid & 31, wid = tid >> 5;
    int mw = wid & 1, nw = wid >> 1;
    int pb[4] = {nw * 32, nw * 32 + 16, 128 + nw * 32, 128 + nw * 32 + 16};
    float acc[4][8][4];
    gemm_main(g_Xh + (size_t)mtb * DD,
              g_Wg + ((size_t)e * FF + (size_t)nt * 128) * DD,
              g_Wu + ((size_t)e * FF + (size_t)nt * 128) * DD,
              DD, DD, DD / 64, sptr(smem), tid, pb, acc);
    // epilogue: j 0-3 gate, j 4-7 up (same cols)
    #pragma unroll
    for (int mt = 0; mt < 4; mt++)
        #pragma unroll
        for (int jg = 0; jg < 4; jg++) {
            int row = mtb + mw * 64 + mt * 16 + (lane >> 2);
            int col = nt * 128 + nw * 32 + jg * 8 + (lane & 3) * 2;
            #pragma unroll
            for (int h = 0; h < 2; h++) {
                float g0 = acc[mt][jg][2 * h], g1 = acc[mt][jg][2 * h + 1];
                float u0 = acc[mt][jg + 4][2 * h], u1 = acc[mt][jg + 4][2 * h + 1];
                float v0 = g0 * u0 / (1.f + __expf(-g0));
                float v1 = g1 * u1 / (1.f + __expf(-g1));
                size_t o = (size_t)(row + h * 8) * FF + col;
                *(__half2*)(g_Hh + o) =
                    __halves2half2(__float2half_rn(v0), __float2half_rn(v1));
            }
        }
}

// ---------------- GEMM2: H @ Wd^T -> scatter fp32 ----------------
__global__ void __launch_bounds__(256, 1) k_gemm2(float* out) {
    extern __shared__ __align__(1024) char smem[];
    int nt = blockIdx.x, mtb = blockIdx.y * 128;
    if (mtb >= g_meta[5]) return;
    int e = (mtb >= g_meta[4]) ? 1 : 0;
    int tid = threadIdx.x, lane = tid & 31, wid = tid >> 5;
    int mw = wid & 1, nw = wid >> 1;
    int pb[4] = {nw * 64, nw * 64 + 16, nw * 64 + 32, nw * 64 + 48};
    const __half* Bd = g_Wd + ((size_t)e * DD + (size_t)nt * 256) * FF;
    float acc[4][8][4];
    gemm_main(g_Hh + (size_t)mtb * FF,
              Bd, Bd + (size_t)128 * FF, FF, FF, FF / 64, sptr(smem), tid, pb, acc);
    #pragma unroll
    for (int mt = 0; mt < 4; mt++) {
        int row = mtb + mw * 64 + mt * 16 + (lane >> 2);
        #pragma unroll
        for (int h = 0; h < 2; h++) {
            int t = g_rows[row + h * 8];
            if (t < 0) continue;
            #pragma unroll
            for (int j = 0; j < 8; j++) {
                int col = nt * 256 + nw * 64 + j * 8 + (lane & 3) * 2;
                float2 v = make_float2(acc[mt][j][2 * h], acc[mt][j][2 * h + 1]);
                *(float2*)(out + (size_t)t * DD + col) = v;
            }
        }
    }
}

// ---------------- launch ----------------
extern "C" void kernel_launch(void* const* d_in, const int* in_sizes, int n_in,
                              void* d_out, int out_size) {
    const float* X = (const float*)d_in[0];
    const int* mask = (const int*)d_in[1];
    const float* wg = (const float*)d_in[2];
    const float* wu = (const float*)d_in[3];
    const float* wd = (const float*)d_in[4];
    float* out = (float*)d_out;

    cudaFuncSetAttribute(k_gemm1, cudaFuncAttributeMaxDynamicSharedMemorySize, 3 * STAGE);
    cudaFuncSetAttribute(k_gemm2, cudaFuncAttributeMaxDynamicSharedMemorySize, 3 * STAGE);

    void *pWg, *pWu, *pWd;
    cudaGetSymbolAddress(&pWg, g_Wg);
    cudaGetSymbolAddress(&pWu, g_Wu);
    cudaGetSymbolAddress(&pWd, g_Wd);

    k_zero<<<1, 1>>>();
    k_count<<<TOK / 256, 256>>>(mask);
    k_metak<<<1, 1>>>();
    k_init<<<(TPAD + 255) / 256, 256>>>();
    k_assign<<<TOK / 256, 256>>>(mask);
    k_xsplit<<<(int)(((size_t)TPAD * DD / 4 + 255) / 256), 256>>>(X);
    dim3 trb(32, 8);
    k_tr<<<dim3(FF / 32, DD / 32, 2), trb>>>(wg, (__half*)pWg, DD, FF);
    k_tr<<<dim3(FF / 32, DD / 32, 2), trb>>>(wu, (__half*)pWu, DD, FF);
    k_tr<<<dim3(DD / 32, FF / 32, 2), trb>>>(wd, (__half*)pWd, FF, DD);
    k_gemm1<<<dim3(FF / 128, TPAD / 128), 256, 3 * STAGE>>>();
    k_gemm2<<<dim3(DD / 256, TPAD / 128), 256, 3 * STAGE>>>(out);
}

// round 11
// speedup vs baseline: 1.0209x; 1.0209x over previous
#include <cuda_runtime.h>
#include <cuda_fp16.h>
#include <cstdint>

#define TOK 16384
#define TPAD 16640
#define DD 2048
#define FF 5632
#define STAGE 49152

// ---------------- device scratch ----------------
__device__ int g_meta[8];          // 0 cnt0, 1 cnt1, 2 pos0, 3 pos1, 4 M0pad, 5 Mtot
__device__ int g_rows[TPAD];
__device__ __align__(128) __half g_Xh[(size_t)TPAD * DD];
__device__ __align__(128) __half g_Wg[(size_t)2 * FF * DD];   // [e][FF][D] K-major
__device__ __align__(128) __half g_Wu[(size_t)2 * FF * DD];
__device__ __align__(128) __half g_Wd[(size_t)2 * DD * FF];   // [e][D][FF] K-major
__device__ __align__(128) __half g_Hh[(size_t)TPAD * FF];

// ---------------- helpers ----------------
__device__ __forceinline__ uint32_t sptr(const void* p) {
    uint32_t a;
    asm("{.reg .u64 t; cvta.to.shared.u64 t,%1; cvt.u32.u64 %0,t;}" : "=r"(a) : "l"(p));
    return a;
}
__device__ __forceinline__ void cpa(uint32_t d, const void* s) {
    asm volatile("cp.async.cg.shared.global [%0],[%1],16;" :: "r"(d), "l"(s));
}
__device__ __forceinline__ void cpcommit() { asm volatile("cp.async.commit_group;"); }
template <int N> __device__ __forceinline__ void cpwait() {
    asm volatile("cp.async.wait_group %0;" :: "n"(N));
}
__device__ __forceinline__ uint32_t sw(uint32_t o) { return o ^ ((o >> 3) & 0x70); }
__device__ __forceinline__ void ldsm4(uint32_t* r, uint32_t a) {
    asm volatile("ldmatrix.sync.aligned.m8n8.x4.shared.b16 {%0,%1,%2,%3},[%4];"
                 : "=r"(r[0]), "=r"(r[1]), "=r"(r[2]), "=r"(r[3]) : "r"(a));
}
__device__ __forceinline__ void mma(float* c, const uint32_t* a, uint32_t b0, uint32_t b1) {
    asm volatile("mma.sync.aligned.m16n8k16.row.col.f32.f16.f16.f32 "
                 "{%0,%1,%2,%3},{%4,%5,%6,%7},{%8,%9},{%0,%1,%2,%3};"
                 : "+f"(c[0]), "+f"(c[1]), "+f"(c[2]), "+f"(c[3])
                 : "r"(a[0]), "r"(a[1]), "r"(a[2]), "r"(a[3]), "r"(b0), "r"(b1));
}

// ---------------- routing (low-atomic-contention) ----------------
__global__ void k_init() {
    int i = blockIdx.x * 256 + threadIdx.x;
    if (i < TPAD) g_rows[i] = -1;
    if (i < 8) g_meta[i] = 0;
}
// 2 atomics per block instead of 256
__global__ void k_count(const int* mask) {
    int tid = threadIdx.x;
    int t = blockIdx.x * 256 + tid;
    int e = mask[t] != 0;
    unsigned b1 = __ballot_sync(0xFFFFFFFFu, e);
    __shared__ int wc[8];
    if ((tid & 31) == 0) wc[tid >> 5] = __popc(b1);
    __syncthreads();
    if (tid == 0) {
        int c1 = 0;
        #pragma unroll
        for (int i = 0; i < 8; i++) c1 += wc[i];
        atomicAdd(&g_meta[1], c1);
        atomicAdd(&g_meta[0], 256 - c1);
    }
}
__global__ void k_metak() {
    int m0 = (g_meta[0] + 127) & ~127, m1 = (g_meta[1] + 127) & ~127;
    g_meta[4] = m0; g_meta[5] = m0 + m1; g_meta[2] = 0; g_meta[3] = m0;
}
// 2 atomics per block + intra-block scan
__global__ void k_assign(const int* mask) {
    int tid = threadIdx.x, lane = tid & 31, w = tid >> 5;
    int t = blockIdx.x * 256 + tid;
    int e = mask[t] != 0;
    unsigned b1 = __ballot_sync(0xFFFFFFFFu, e);
    __shared__ int s1[8], sb[2];
    if (lane == 0) s1[w] = __popc(b1);
    __syncthreads();
    if (tid == 0) {
        int acc = 0;
        #pragma unroll
        for (int i = 0; i < 8; i++) { int c = s1[i]; s1[i] = acc; acc += c; }
        sb[1] = atomicAdd(&g_meta[3], acc);
        sb[0] = atomicAdd(&g_meta[2], 256 - acc);
    }
    __syncthreads();
    unsigned lt = (1u << lane) - 1u;
    int r1 = __popc(b1 & lt);
    int row = e ? sb[1] + s1[w] + r1
                : sb[0] + 32 * w - s1[w] + (lane - r1);
    g_rows[row] = t;
}
__global__ void k_xsplit(const float* X) {
    size_t i = (size_t)blockIdx.x * 256 + threadIdx.x;
    size_t row = i / (DD / 4);
    int c4 = (int)(i % (DD / 4));
    if (row >= (size_t)g_meta[5]) return;
    int t = g_rows[row];
    float4 v = t >= 0 ? ((const float4*)X)[(size_t)t * (DD / 4) + c4] : make_float4(0, 0, 0, 0);
    size_t o = row * DD + (size_t)c4 * 4;
    *(__half2*)(g_Xh + o) = __halves2half2(__float2half_rn(v.x), __float2half_rn(v.y));
    *(__half2*)(g_Xh + o + 2) = __halves2half2(__float2half_rn(v.z), __float2half_rn(v.w));
}
// transpose+convert: src fp32 [R,C] -> dst fp16 [C,R], per expert (z)
__global__ void k_tr(const float* src, __half* dst, int R, int C) {
    __shared__ float t[32][33];
    size_t eo = (size_t)blockIdx.z * R * C;
    src += eo; dst += eo;
    int c0 = blockIdx.x * 32, r0 = blockIdx.y * 32;
    int x = threadIdx.x, y = threadIdx.y;
    for (int i = y; i < 32; i += 8) t[i][x] = src[(size_t)(r0 + i) * C + c0 + x];
    __syncthreads();
    for (int i = y; i < 32; i += 8) dst[(size_t)(c0 + i) * R + r0 + x] = __float2half_rn(t[x][i]);
}

// ---------------- shared GEMM core (r8 best-measured config) ----------------
// 512 threads, 16 warps (4m x 4n), warptile 32x64.
// smem stage (48KB): A[128x64h]@0, B[256x64h]@16K. 2 stages.
__device__ __forceinline__ void gemm_main(
    const __half* A0, const __half* B0, const __half* B1,
    int lda, int ldb, int NK, uint32_t sb, int tid, const int* pb,
    float acc[2][8][4])
{
    int lane = tid & 31, wid = tid >> 5, mw = wid & 3;
    #pragma unroll
    for (int a = 0; a < 2; a++)
        #pragma unroll
        for (int j = 0; j < 8; j++)
            #pragma unroll
            for (int q = 0; q < 4; q++) acc[a][j][q] = 0.f;

    auto load = [&](int kc) {
        uint32_t st = sb + (kc & 1) * STAGE;
        int k0 = kc * 64;
        #pragma unroll
        for (int i = tid; i < 1024; i += 512) {
            int r = i >> 3, u = i & 7;
            cpa(st + sw(r * 128 + u * 16), A0 + (size_t)r * lda + k0 + u * 8);
        }
        #pragma unroll
        for (int i = tid; i < 2048; i += 512) {
            int r = i >> 3, u = i & 7;
            const __half* s = (r < 128) ? B0 + (size_t)r * ldb + k0 + u * 8
                                        : B1 + (size_t)(r - 128) * ldb + k0 + u * 8;
            cpa(st + 16384 + sw(r * 128 + u * 16), s);
        }
        cpcommit();
    };

    load(0);
    int ar = mw * 32 + (lane & 7) + ((lane >> 3) & 1) * 8;
    int akb = ((lane >> 4) & 1) * 16;
    int br = (lane & 7) + ((lane >> 4) & 1) * 8;
    int bkb = ((lane >> 3) & 1) * 16;

    for (int kc = 0; kc < NK; kc++) {
        if (kc + 1 < NK) { load(kc + 1); cpwait<1>(); }
        else cpwait<0>();
        __syncthreads();
        uint32_t st = sb + (kc & 1) * STAGE;
        #pragma unroll
        for (int ks = 0; ks < 4; ks++) {
            uint32_t ah0[4], ah1[4];
            int kb = ks * 32;
            ldsm4(ah0, st + sw(ar * 128 + kb + akb));
            ldsm4(ah1, st + sw((ar + 16) * 128 + kb + akb));
            #pragma unroll
            for (int p = 0; p < 4; p++) {
                uint32_t bb[4];
                ldsm4(bb, st + 16384 + sw((pb[p] + br) * 128 + kb + bkb));
                #pragma unroll
                for (int h = 0; h < 2; h++) {
                    int j = 2 * p + h;
                    mma(acc[0][j], ah0, bb[2 * h], bb[2 * h + 1]);
                    mma(acc[1][j], ah1, bb[2 * h], bb[2 * h + 1]);
                }
            }
        }
        __syncthreads();
    }
}

// ---------------- GEMM1: X @ {Wg,Wu}^T -> SwiGLU -> H ----------------
__global__ void __launch_bounds__(512, 1) k_gemm1() {
    extern __shared__ __align__(1024) char smem[];
    int nt = blockIdx.x, mtb = blockIdx.y * 128;
    if (mtb >= g_meta[5]) return;
    int e = (mtb >= g_meta[4]) ? 1 : 0;
    int tid = threadIdx.x, lane = tid & 31, wid = tid >> 5;
    int mw = wid & 3, nw = wid >> 2;
    int pb[4] = {nw * 32, nw * 32 + 16, 128 + nw * 32, 128 + nw * 32 + 16};
    float acc[2][8][4];
    gemm_main(g_Xh + (size_t)mtb * DD,
              g_Wg + ((size_t)e * FF + (size_t)nt * 128) * DD,
              g_Wu + ((size_t)e * FF + (size_t)nt * 128) * DD,
              DD, DD, DD / 64, sptr(smem), tid, pb, acc);
    // epilogue: j 0-3 gate, j 4-7 up (same cols)
    #pragma unroll
    for (int mt = 0; mt < 2; mt++)
        #pragma unroll
        for (int jg = 0; jg < 4; jg++) {
            int row = mtb + mw * 32 + mt * 16 + (lane >> 2);
            int col = nt * 128 + nw * 32 + jg * 8 + (lane & 3) * 2;
            #pragma unroll
            for (int h = 0; h < 2; h++) {
                float g0 = acc[mt][jg][2 * h], g1 = acc[mt][jg][2 * h + 1];
                float u0 = acc[mt][jg + 4][2 * h], u1 = acc[mt][jg + 4][2 * h + 1];
                float v0 = g0 * u0 / (1.f + __expf(-g0));
                float v1 = g1 * u1 / (1.f + __expf(-g1));
                size_t o = (size_t)(row + h * 8) * FF + col;
                *(__half2*)(g_Hh + o) =
                    __halves2half2(__float2half_rn(v0), __float2half_rn(v1));
            }
        }
}

// ---------------- GEMM2: H @ Wd^T -> scatter fp32 ----------------
__global__ void __launch_bounds__(512, 1) k_gemm2(float* out) {
    extern __shared__ __align__(1024) char smem[];
    int nt = blockIdx.x, mtb = blockIdx.y * 128;
    if (mtb >= g_meta[5]) return;
    int e = (mtb >= g_meta[4]) ? 1 : 0;
    int tid = threadIdx.x, lane = tid & 31, wid = tid >> 5;
    int mw = wid & 3, nw = wid >> 2;
    int pb[4] = {nw * 64, nw * 64 + 16, nw * 64 + 32, nw * 64 + 48};
    const __half* Bd = g_Wd + ((size_t)e * DD + (size_t)nt * 256) * FF;
    float acc[2][8][4];
    gemm_main(g_Hh + (size_t)mtb * FF,
              Bd, Bd + (size_t)128 * FF, FF, FF, FF / 64, sptr(smem), tid, pb, acc);
    #pragma unroll
    for (int mt = 0; mt < 2; mt++) {
        int row = mtb + mw * 32 + mt * 16 + (lane >> 2);
        #pragma unroll
        for (int h = 0; h < 2; h++) {
            int t = g_rows[row + h * 8];
            if (t < 0) continue;
            #pragma unroll
            for (int j = 0; j < 8; j++) {
                int col = nt * 256 + nw * 64 + j * 8 + (lane & 3) * 2;
                float2 v = make_float2(acc[mt][j][2 * h], acc[mt][j][2 * h + 1]);
                *(float2*)(out + (size_t)t * DD + col) = v;
            }
        }
    }
}

// ---------------- launch ----------------
extern "C" void kernel_launch(void* const* d_in, const int* in_sizes, int n_in,
                              void* d_out, int out_size) {
    const float* X = (const float*)d_in[0];
    const int* mask = (const int*)d_in[1];
    const float* wg = (const float*)d_in[2];
    const float* wu = (const float*)d_in[3];
    const float* wd = (const float*)d_in[4];
    float* out = (float*)d_out;

    cudaFuncSetAttribute(k_gemm1, cudaFuncAttributeMaxDynamicSharedMemorySize, 2 * STAGE);
    cudaFuncSetAttribute(k_gemm2, cudaFuncAttributeMaxDynamicSharedMemorySize, 2 * STAGE);

    void *pWg, *pWu, *pWd;
    cudaGetSymbolAddress(&pWg, g_Wg);
    cudaGetSymbolAddress(&pWu, g_Wu);
    cudaGetSymbolAddress(&pWd, g_Wd);

    k_init<<<(TPAD + 255) / 256, 256>>>();
    k_count<<<TOK / 256, 256>>>(mask);
    k_metak<<<1, 1>>>();
    k_assign<<<TOK / 256, 256>>>(mask);
    k_xsplit<<<(int)(((size_t)TPAD * DD / 4 + 255) / 256), 256>>>(X);
    dim3 trb(32, 8);
    k_tr<<<dim3(FF / 32, DD / 32, 2), trb>>>(wg, (__half*)pWg, DD, FF);
    k_tr<<<dim3(FF / 32, DD / 32, 2), trb>>>(wu, (__half*)pWu, DD, FF);
    k_tr<<<dim3(DD / 32, FF / 32, 2), trb>>>(wd, (__half*)pWd, FF, DD);
    k_gemm1<<<dim3(FF / 128, TPAD / 128), 512, 2 * STAGE>>>();
    k_gemm2<<<dim3(DD / 256, TPAD / 128), 512, 2 * STAGE>>>(out);
}